// round 10
// baseline (speedup 1.0000x reference)
#include <cuda_runtime.h>
#include <cuda_bf16.h>
#include <cstdint>

#define NTH   512                        // 16 warps: 8 m-blocks x 2 n-halves
#define PTH   512
#define ST    136                        // bf16 per weight-tile row (272 B stride)
#define TILEB (128 * ST * 2)             // 34816 B per 128x128 bf16 tile
#define EDGE_SMEM (6 * TILEB)            // W1a'(h,l) W1b(h,l) W2(h,l) = 208896
#define NODE_SMEM (4 * TILEB)            // U(h,l) V(h,l) = 139264
#define NODE_PAD 100096

// ---------------- device scratch (static, allowed) ----------------
__device__ __align__(16) float gVU[(size_t)NODE_PAD * 128];
__device__ __align__(16) float gVV[(size_t)NODE_PAD * 128];
__device__ __align__(16) float gW1a[128 * 128];
__device__ __align__(16) float gB1p[128];
__device__ __align__(16) char  gWimg[3][2][TILEB];          // 0:W1a' 1:W1b 2:W2
__device__ __align__(16) uint4 gXch[160][8][32][32];        // [block][mb][lane][slot]

// ---------------- PTX helpers ----------------
__device__ __forceinline__ uint32_t smem_u32(const void* p) {
    uint32_t a;
    asm("{ .reg .u64 t; cvta.to.shared.u64 t, %1; cvt.u32.u64 %0, t; }" : "=r"(a) : "l"(p));
    return a;
}
#define LDSM4(r, addr)                                                              \
    asm volatile("ldmatrix.sync.aligned.m8n8.x4.shared.b16 {%0,%1,%2,%3}, [%4];"    \
                 : "=r"((r)[0]), "=r"((r)[1]), "=r"((r)[2]), "=r"((r)[3])           \
                 : "r"(addr))
__device__ __forceinline__ void mma_bf16(float* c, const uint32_t* a, uint32_t b0, uint32_t b1) {
    asm volatile("mma.sync.aligned.m16n8k16.row.col.f32.bf16.bf16.f32 "
                 "{%0,%1,%2,%3}, {%4,%5,%6,%7}, {%8,%9}, {%0,%1,%2,%3};"
                 : "+f"(c[0]), "+f"(c[1]), "+f"(c[2]), "+f"(c[3])
                 : "r"(a[0]), "r"(a[1]), "r"(a[2]), "r"(a[3]), "r"(b0), "r"(b1));
}
#define CP16(dst, src) \
    asm volatile("cp.async.ca.shared.global [%0], [%1], 16;" :: "r"(dst), "l"(src))
#define CP_COMMIT() asm volatile("cp.async.commit_group;" ::: "memory")
#define CP_WAIT()   asm volatile("cp.async.wait_group 0;" ::: "memory")

// ---------------- numeric helpers ----------------
__device__ __forceinline__ float bf16hi_rn(float a, uint32_t& hbits) {
    uint32_t u = __float_as_uint(a);
    uint32_t r = (u + 0x7FFFu + ((u >> 16) & 1u)) & 0xFFFF0000u;
    hbits = r;
    return __uint_as_float(r);
}
__device__ __forceinline__ uint32_t bf16x2_of(float lo, float hi) {
    uint32_t r;
    asm("cvt.rn.bf16x2.f32 %0, %1, %2;" : "=r"(r) : "f"(hi), "f"(lo));
    return r;
}
__device__ __forceinline__ void split2(float x, float y, uint32_t& h, uint32_t& l) {
    uint32_t rx, ry;
    float hx = bf16hi_rn(x, rx), hy = bf16hi_rn(y, ry);
    h = __byte_perm(rx, ry, 0x7632);
    l = bf16x2_of(x - hx, y - hy);
}
__device__ __forceinline__ float fast_tanh(float x) {
    float e = __expf(2.f * x);
    return 1.f - __fdividef(2.f, e + 1.f);
}
__device__ __forceinline__ float lk(float v) { return v > 0.f ? v : 0.01f * v; }

__device__ __forceinline__ void stage32(const float* __restrict__ src,
                                        char* Xh, char* Xl, uint32_t off) {
    #pragma unroll
    for (int i = 0; i < 8; ++i) {
        float4 t = reinterpret_cast<const float4*>(src)[i];
        uint32_t r0, r1, r2, r3;
        float h0 = bf16hi_rn(t.x, r0), h1 = bf16hi_rn(t.y, r1);
        float h2 = bf16hi_rn(t.z, r2), h3 = bf16hi_rn(t.w, r3);
        uint2 hh = make_uint2(__byte_perm(r0, r1, 0x7632), __byte_perm(r2, r3, 0x7632));
        uint2 ll = make_uint2(bf16x2_of(t.x - h0, t.y - h1), bf16x2_of(t.z - h2, t.w - h3));
        *reinterpret_cast<uint2*>(Xh + off + i * 8) = hh;
        *reinterpret_cast<uint2*>(Xl + off + i * 8) = ll;
    }
}

// one n-group (n=16), 3-term split with preloaded B frags
__device__ __forceinline__ void mma6(float* acc, const uint32_t* ah, const uint32_t* al,
                                     const uint32_t* bh, const uint32_t* bl) {
    mma_bf16(acc,     ah, bh[0], bh[1]);
    mma_bf16(acc,     ah, bl[0], bl[1]);
    mma_bf16(acc,     al, bh[0], bh[1]);
    mma_bf16(acc + 4, ah, bh[2], bh[3]);
    mma_bf16(acc + 4, ah, bl[2], bl[3]);
    mma_bf16(acc + 4, al, bh[2], bh[3]);
}

// ================= prep 1: W1a' = W1a @ P_w, b1' = b1 + W1a @ P_b =================
__global__ void __launch_bounds__(PTH, 1)
ecat_compose(const float* __restrict__ W1, const float* __restrict__ P_w,
             const float* __restrict__ P_b, const float* __restrict__ b1)
{
    int tid = threadIdx.x;
    int o = tid >> 2, jb = (tid & 3) * 32;
    float acc[32];
    #pragma unroll
    for (int j = 0; j < 32; ++j) acc[j] = 0.f;
    for (int i = 0; i < 128; ++i) {
        float w = W1[o * 256 + i];
        const float4* pr = reinterpret_cast<const float4*>(P_w + i * 128 + jb);
        #pragma unroll
        for (int j = 0; j < 8; ++j) {
            float4 p = pr[j];
            acc[4*j]   += w * p.x; acc[4*j+1] += w * p.y;
            acc[4*j+2] += w * p.z; acc[4*j+3] += w * p.w;
        }
    }
    #pragma unroll
    for (int j = 0; j < 8; ++j)
        reinterpret_cast<float4*>(gW1a + o * 128 + jb)[j] =
            make_float4(acc[4*j], acc[4*j+1], acc[4*j+2], acc[4*j+3]);
    if ((tid & 3) == 0) {
        float s = 0.f;
        for (int i = 0; i < 128; ++i) s += W1[o * 256 + i] * P_b[i];
        gB1p[o] = b1[o] + s;
    }
}

// ================= prep 2: edge weight tiles -> bf16 hi/lo smem images =================
__global__ void __launch_bounds__(PTH, 1)
ecat_convert(const float* __restrict__ W1, const float* __restrict__ W2)
{
    int b = blockIdx.x;
    int tid = threadIdx.x;
    int o = tid >> 2, qo = (tid & 3) * 32;
    const float* srcRow;
    if (b == 0)      srcRow = gW1a + o * 128 + qo;
    else if (b == 1) srcRow = W1 + o * 256 + 128 + qo;
    else             srcRow = W2 + o * 128 + qo;
    stage32(srcRow, (char*)gWimg[b][0], (char*)gWimg[b][1], (uint32_t)(o * ST + qo) * 2);
}

// ================= node kernel: VU & VV in ONE pass, 8m x 2n warp grid =================
__global__ void __launch_bounds__(NTH, 1)
ecat_node(const float* __restrict__ V, const float* __restrict__ U_w,
          const float* __restrict__ V_w, int n_nodes, int n_ntiles)
{
    extern __shared__ char sm[];
    char* sUh = sm;               char* sUl = sm + TILEB;
    char* sVh = sm + 2 * TILEB;   char* sVl = sm + 3 * TILEB;
    const uint32_t uUh = smem_u32(sUh), uUl = smem_u32(sUl);
    const uint32_t uVh = smem_u32(sVh), uVl = smem_u32(sVl);

    const int tid = threadIdx.x;
    {   // self-convert weights: each thread handles one row-quarter of each matrix
        int o = tid >> 2, qo = (tid & 3) * 32;
        uint32_t off = (uint32_t)(o * ST + qo) * 2;
        stage32(U_w + (size_t)o * 128 + qo, sUh, sUl, off);
        stage32(V_w + (size_t)o * 128 + qo, sVh, sVl, off);
    }
    __syncthreads();

    const int lane = tid & 31, w = tid >> 5;
    const int mb = w & 7, h = w >> 3;
    const int r0 = lane >> 2, il = lane & 3, cb = il * 2;
    const uint32_t nBase = (uint32_t)h * 64 * (ST * 2);
    const uint32_t offB = (uint32_t)(((lane & 7) + (((lane >> 4) & 1) << 3)) * ST
                                     + (((lane >> 3) & 1) << 3)) * 2;

    for (int t = blockIdx.x; t < n_ntiles; t += gridDim.x) {
        int n0 = t * 128 + mb * 16 + r0;
        int n1 = n0 + 8;
        int n0c = n0 < n_nodes ? n0 : 0;
        int n1c = n1 < n_nodes ? n1 : 0;
        const float2* pa0 = reinterpret_cast<const float2*>(V + (size_t)n0c * 128);
        const float2* pa1 = reinterpret_cast<const float2*>(V + (size_t)n1c * 128);

        float accU[32], accV[32];
        #pragma unroll
        for (int i = 0; i < 32; ++i) { accU[i] = 0.f; accV[i] = 0.f; }

        #pragma unroll 1
        for (int ks = 0; ks < 8; ++ks) {
            int i0 = il + 8 * ks, i1 = i0 + 4;
            uint32_t ah[4], al[4];
            float2 a0 = pa0[i0], b0 = pa1[i0], c0 = pa0[i1], d0 = pa1[i1];
            split2(a0.x, a0.y, ah[0], al[0]);
            split2(b0.x, b0.y, ah[1], al[1]);
            split2(c0.x, c0.y, ah[2], al[2]);
            split2(d0.x, d0.y, ah[3], al[3]);
            const uint32_t kb = nBase + offB + ks * 32;
            #pragma unroll
            for (int g = 0; g < 4; ++g) {
                uint32_t go = (uint32_t)g * (16 * ST * 2);
                uint32_t bh[4], bl[4];
                LDSM4(bh, uUh + kb + go);
                LDSM4(bl, uUl + kb + go);
                mma6(accU + 8 * g, ah, al, bh, bl);
                LDSM4(bh, uVh + kb + go);
                LDSM4(bl, uVl + kb + go);
                mma6(accV + 8 * g, ah, al, bh, bl);
            }
        }
        #pragma unroll
        for (int nf = 0; nf < 8; ++nf) {
            int c = h * 64 + nf * 8 + cb;
            if (n0 < n_nodes) {
                *reinterpret_cast<float2*>(gVU + (size_t)n0 * 128 + c) =
                    make_float2(accU[nf*4], accU[nf*4+1]);
                *reinterpret_cast<float2*>(gVV + (size_t)n0 * 128 + c) =
                    make_float2(accV[nf*4], accV[nf*4+1]);
            }
            if (n1 < n_nodes) {
                *reinterpret_cast<float2*>(gVU + (size_t)n1 * 128 + c) =
                    make_float2(accU[nf*4+2], accU[nf*4+3]);
                *reinterpret_cast<float2*>(gVV + (size_t)n1 * 128 + c) =
                    make_float2(accV[nf*4+2], accV[nf*4+3]);
            }
        }
    }
}

// ================= main edge kernel: 8m x 2n warps, y-exchange via L2 scratch =================
__global__ void __launch_bounds__(NTH, 1)
ecat_edge(const float* __restrict__ E, const int* __restrict__ src,
          const int* __restrict__ dst, const float* __restrict__ b2,
          float* __restrict__ out, int n_tiles)
{
    extern __shared__ char sm[];
    uint32_t smb = smem_u32(sm);
    const char* gsrc = &gWimg[0][0][0];
    #pragma unroll
    for (int i = 0; i < 26; ++i) {
        int idx = i * NTH + threadIdx.x;
        if (idx < 6 * TILEB / 16) CP16(smb + idx * 16, gsrc + idx * 16);
    }
    CP_COMMIT(); CP_WAIT();
    __syncthreads();

    const int tid = threadIdx.x, lane = tid & 31, w = tid >> 5;
    const int mb = w & 7, h = w >> 3;
    const int r0 = lane >> 2, il = lane & 3, cb = il * 2;
    const uint32_t nBase = (uint32_t)h * 64 * (ST * 2);
    const uint32_t offB = (uint32_t)(((lane & 7) + (((lane >> 4) & 1) << 3)) * ST
                                     + (((lane >> 3) & 1) << 3)) * 2;
    const uint32_t uW1aH = smb,             uW1aL = smb + TILEB;
    const uint32_t uW1bH = smb + 2 * TILEB, uW1bL = smb + 3 * TILEB;
    const uint32_t uW2H  = smb + 4 * TILEB, uW2L  = smb + 5 * TILEB;
    uint4* gx = &gXch[blockIdx.x][mb][lane][0];

    for (int t = blockIdx.x; t < n_tiles; t += gridDim.x) {
        long eb = (long)t * 256 + mb * 32 + r0;   // edge rows eb + 8q, q=0..3
        const float2* pu[4];
        const float2* pv[4];
        #pragma unroll
        for (int q = 0; q < 4; ++q) {
            long er = eb + q * 8;
            pu[q] = reinterpret_cast<const float2*>(gVU + (size_t)__ldg(src + er) * 128);
            pv[q] = reinterpret_cast<const float2*>(gVV + (size_t)__ldg(dst + er) * 128);
        }
        const float2* pe = reinterpret_cast<const float2*>(E + eb * 128);

        float acc0[32], acc1[32];
        #pragma unroll
        for (int i = 0; i < 32; ++i) { acc0[i] = 0.f; acc1[i] = 0.f; }

        // ---- GEMM A: tanh stream @ W1a' (warp's n-half only) ----
        #pragma unroll 1
        for (int ks = 0; ks < 8; ++ks) {
            int i0 = il + 8 * ks, i1 = i0 + 4;
            uint32_t ah0[4], al0[4], ah1[4], al1[4];
            {
                float2 u0 = pu[0][i0], u1 = pu[1][i0], u2 = pu[0][i1], u3 = pu[1][i1];
                float2 v0 = pv[0][i0], v1 = pv[1][i0], v2 = pv[0][i1], v3 = pv[1][i1];
                split2(fast_tanh(u0.x * v0.x), fast_tanh(u0.y * v0.y), ah0[0], al0[0]);
                split2(fast_tanh(u1.x * v1.x), fast_tanh(u1.y * v1.y), ah0[1], al0[1]);
                split2(fast_tanh(u2.x * v2.x), fast_tanh(u2.y * v2.y), ah0[2], al0[2]);
                split2(fast_tanh(u3.x * v3.x), fast_tanh(u3.y * v3.y), ah0[3], al0[3]);
            }
            {
                float2 u0 = pu[2][i0], u1 = pu[3][i0], u2 = pu[2][i1], u3 = pu[3][i1];
                float2 v0 = pv[2][i0], v1 = pv[3][i0], v2 = pv[2][i1], v3 = pv[3][i1];
                split2(fast_tanh(u0.x * v0.x), fast_tanh(u0.y * v0.y), ah1[0], al1[0]);
                split2(fast_tanh(u1.x * v1.x), fast_tanh(u1.y * v1.y), ah1[1], al1[1]);
                split2(fast_tanh(u2.x * v2.x), fast_tanh(u2.y * v2.y), ah1[2], al1[2]);
                split2(fast_tanh(u3.x * v3.x), fast_tanh(u3.y * v3.y), ah1[3], al1[3]);
            }
            const uint32_t kb = nBase + offB + ks * 32;
            #pragma unroll
            for (int g = 0; g < 4; ++g) {
                uint32_t go = (uint32_t)g * (16 * ST * 2);
                uint32_t bh[4], bl[4];
                LDSM4(bh, uW1aH + kb + go);
                LDSM4(bl, uW1aL + kb + go);
                mma6(acc0 + 8 * g, ah0, al0, bh, bl);
                mma6(acc1 + 8 * g, ah1, al1, bh, bl);
            }
        }
        // ---- GEMM B: leaky(E) stream @ W1b ----
        #pragma unroll 1
        for (int ks = 0; ks < 8; ++ks) {
            int i0 = il + 8 * ks, i1 = i0 + 4;
            uint32_t ah0[4], al0[4], ah1[4], al1[4];
            {
                float2 e0 = pe[i0],        e1 = pe[512 + i0];
                float2 e2 = pe[i1],        e3 = pe[512 + i1];
                split2(lk(e0.x), lk(e0.y), ah0[0], al0[0]);
                split2(lk(e1.x), lk(e1.y), ah0[1], al0[1]);
                split2(lk(e2.x), lk(e2.y), ah0[2], al0[2]);
                split2(lk(e3.x), lk(e3.y), ah0[3], al0[3]);
                float2 f0 = pe[1024 + i0], f1 = pe[1536 + i0];
                float2 f2 = pe[1024 + i1], f3 = pe[1536 + i1];
                split2(lk(f0.x), lk(f0.y), ah1[0], al1[0]);
                split2(lk(f1.x), lk(f1.y), ah1[1], al1[1]);
                split2(lk(f2.x), lk(f2.y), ah1[2], al1[2]);
                split2(lk(f3.x), lk(f3.y), ah1[3], al1[3]);
            }
            const uint32_t kb = nBase + offB + ks * 32;
            #pragma unroll
            for (int g = 0; g < 4; ++g) {
                uint32_t go = (uint32_t)g * (16 * ST * 2);
                uint32_t bh[4], bl[4];
                LDSM4(bh, uW1bH + kb + go);
                LDSM4(bl, uW1bL + kb + go);
                mma6(acc0 + 8 * g, ah0, al0, bh, bl);
                mma6(acc1 + 8 * g, ah1, al1, bh, bl);
            }
        }

        // ---- y1 = relu(acc + b1') -> A-frags for this warp's k-range; publish to L2 ----
        #pragma unroll
        for (int b = 0; b < 2; ++b) {
            const float* A = b ? acc1 : acc0;
            #pragma unroll
            for (int kl = 0; kl < 4; ++kl) {
                int nf0 = 2 * kl, nf1 = 2 * kl + 1;
                float2 bb0 = __ldg(reinterpret_cast<const float2*>(gB1p + h * 64 + nf0 * 8 + cb));
                float2 bb1 = __ldg(reinterpret_cast<const float2*>(gB1p + h * 64 + nf1 * 8 + cb));
                uint4 H, L;
                split2(fmaxf(A[nf0*4+0] + bb0.x, 0.f), fmaxf(A[nf0*4+1] + bb0.y, 0.f), H.x, L.x);
                split2(fmaxf(A[nf0*4+2] + bb0.x, 0.f), fmaxf(A[nf0*4+3] + bb0.y, 0.f), H.y, L.y);
                split2(fmaxf(A[nf1*4+0] + bb1.x, 0.f), fmaxf(A[nf1*4+1] + bb1.y, 0.f), H.z, L.z);
                split2(fmaxf(A[nf1*4+2] + bb1.x, 0.f), fmaxf(A[nf1*4+3] + bb1.y, 0.f), H.w, L.w);
                int slot = (b * 8 + h * 4 + kl) * 2;
                gx[slot]     = H;
                gx[slot + 1] = L;
            }
        }
        __syncthreads();   // all y-frags of the tile visible block-wide

        // ---- GEMM C: two m16 passes, full k from exchange, n-half output ----
        #pragma unroll 1
        for (int b = 0; b < 2; ++b) {
            uint32_t yh[8][4], yl[8][4];
            #pragma unroll
            for (int ks = 0; ks < 8; ++ks) {
                uint4 H = gx[(b * 8 + ks) * 2];
                uint4 L = gx[(b * 8 + ks) * 2 + 1];
                yh[ks][0] = H.x; yh[ks][1] = H.y; yh[ks][2] = H.z; yh[ks][3] = H.w;
                yl[ks][0] = L.x; yl[ks][1] = L.y; yl[ks][2] = L.z; yl[ks][3] = L.w;
            }
            float acc2[32];
            #pragma unroll
            for (int i = 0; i < 32; ++i) acc2[i] = 0.f;
            #pragma unroll 1
            for (int ks = 0; ks < 8; ++ks) {
                const uint32_t kb = nBase + offB + ks * 32;
                #pragma unroll
                for (int g = 0; g < 4; ++g) {
                    uint32_t go = (uint32_t)g * (16 * ST * 2);
                    uint32_t bh[4], bl[4];
                    LDSM4(bh, uW2H + kb + go);
                    LDSM4(bl, uW2L + kb + go);
                    mma6(acc2 + 8 * g, yh[ks], yl[ks], bh, bl);
                }
            }
            long rb = eb + 16 * b;
            #pragma unroll
            for (int nf = 0; nf < 8; ++nf) {
                int c = h * 64 + nf * 8 + cb;
                float2 bb = __ldg(reinterpret_cast<const float2*>(b2 + c));
                *reinterpret_cast<float2*>(out + rb * 128 + c) =
                    make_float2(fmaxf(acc2[nf*4+0] + bb.x, 0.f),
                                fmaxf(acc2[nf*4+1] + bb.y, 0.f));
                *reinterpret_cast<float2*>(out + (rb + 8) * 128 + c) =
                    make_float2(fmaxf(acc2[nf*4+2] + bb.x, 0.f),
                                fmaxf(acc2[nf*4+3] + bb.y, 0.f));
            }
        }
        __syncthreads();   // protect gXch before next tile overwrites
    }
}

// ================= host =================
extern "C" void kernel_launch(void* const* d_in, const int* in_sizes, int n_in,
                              void* d_out, int out_size)
{
    const float* V   = (const float*)d_in[0];
    const float* E   = (const float*)d_in[1];
    const int*   src = (const int*)d_in[2];
    const int*   dst = (const int*)d_in[3];
    const float* U_w = (const float*)d_in[4];
    const float* V_w = (const float*)d_in[5];
    const float* P_w = (const float*)d_in[6];
    const float* P_b = (const float*)d_in[7];
    const float* W1  = (const float*)d_in[8];
    const float* b1  = (const float*)d_in[9];
    const float* W2  = (const float*)d_in[10];
    const float* b2  = (const float*)d_in[11];
    float* out = (float*)d_out;

    int n_nodes = in_sizes[0] / 128;
    int n_edges = in_sizes[2];
    int n_tiles = n_edges / 256;                 // 2500
    int n_ntiles = (n_nodes + 127) / 128;        // 782

    static int sms = 0;
    if (!sms) {
        cudaDeviceGetAttribute(&sms, cudaDevAttrMultiProcessorCount, 0);
        if (sms > 160) sms = 160;                // gXch bound
        cudaFuncSetAttribute(ecat_node, cudaFuncAttributeMaxDynamicSharedMemorySize, NODE_SMEM);
        cudaFuncSetAttribute(ecat_edge, cudaFuncAttributeMaxDynamicSharedMemorySize, EDGE_SMEM);
    }

    ecat_compose<<<1, PTH>>>(W1, P_w, P_b, b1);
    ecat_convert<<<3, PTH>>>(W1, W2);
    ecat_node<<<sms, NTH, NODE_SMEM>>>(V, U_w, V_w, n_nodes, n_ntiles);
    ecat_edge<<<sms, NTH, EDGE_SMEM>>>(E, src, dst, b2, out, n_tiles);
}

// round 11
// speedup vs baseline: 2.0458x; 2.0458x over previous
#include <cuda_runtime.h>
#include <cuda_bf16.h>
#include <cstdint>

#define NTH   512                        // main kernels: 16 warps, m=16 per warp
#define PTH   512
#define ST    136                        // bf16 per weight-tile row (272 B stride)
#define TILEB (128 * ST * 2)             // 34816 B per 128x128 bf16 tile
#define EDGE_SMEM (6 * TILEB)            // W1a'(h,l) W1b(h,l) W2(h,l) = 208896
#define NODE_SMEM (4 * TILEB)            // U(h,l) V(h,l) = 139264
#define NODE_PAD 100096

// ---------------- device scratch (static, allowed) ----------------
__device__ __align__(16) float gVU[(size_t)NODE_PAD * 128];
__device__ __align__(16) float gVV[(size_t)NODE_PAD * 128];
__device__ __align__(16) float gB1p[128];
__device__ __align__(16) char  gWimg[5][2][TILEB];  // 0:W1a' 1:W1b 2:W2 3:U_w 4:V_w

// ---------------- PTX helpers ----------------
__device__ __forceinline__ uint32_t smem_u32(const void* p) {
    uint32_t a;
    asm("{ .reg .u64 t; cvta.to.shared.u64 t, %1; cvt.u32.u64 %0, t; }" : "=r"(a) : "l"(p));
    return a;
}
#define LDSM4(r, addr)                                                              \
    asm volatile("ldmatrix.sync.aligned.m8n8.x4.shared.b16 {%0,%1,%2,%3}, [%4];"    \
                 : "=r"((r)[0]), "=r"((r)[1]), "=r"((r)[2]), "=r"((r)[3])           \
                 : "r"(addr))
__device__ __forceinline__ void mma_bf16(float* c, const uint32_t* a, uint32_t b0, uint32_t b1) {
    asm volatile("mma.sync.aligned.m16n8k16.row.col.f32.bf16.bf16.f32 "
                 "{%0,%1,%2,%3}, {%4,%5,%6,%7}, {%8,%9}, {%0,%1,%2,%3};"
                 : "+f"(c[0]), "+f"(c[1]), "+f"(c[2]), "+f"(c[3])
                 : "r"(a[0]), "r"(a[1]), "r"(a[2]), "r"(a[3]), "r"(b0), "r"(b1));
}
#define CP16(dst, src) \
    asm volatile("cp.async.ca.shared.global [%0], [%1], 16;" :: "r"(dst), "l"(src))
#define CP_COMMIT() asm volatile("cp.async.commit_group;" ::: "memory")
#define CP_WAIT()   asm volatile("cp.async.wait_group 0;" ::: "memory")

// ---------------- numeric helpers ----------------
__device__ __forceinline__ float bf16hi_rn(float a, uint32_t& hbits) {
    uint32_t u = __float_as_uint(a);
    uint32_t r = (u + 0x7FFFu + ((u >> 16) & 1u)) & 0xFFFF0000u;
    hbits = r;
    return __uint_as_float(r);
}
__device__ __forceinline__ uint32_t bf16x2_of(float lo, float hi) {
    uint32_t r;
    asm("cvt.rn.bf16x2.f32 %0, %1, %2;" : "=r"(r) : "f"(hi), "f"(lo));
    return r;
}
__device__ __forceinline__ void split2(float x, float y, uint32_t& h, uint32_t& l) {
    uint32_t rx, ry;
    float hx = bf16hi_rn(x, rx), hy = bf16hi_rn(y, ry);
    h = __byte_perm(rx, ry, 0x7632);
    l = bf16x2_of(x - hx, y - hy);
}
__device__ __forceinline__ float fast_tanh(float x) {
    float e = __expf(2.f * x);
    return 1.f - __fdividef(2.f, e + 1.f);
}
__device__ __forceinline__ float lk(float v) { return v > 0.f ? v : 0.01f * v; }

__device__ __forceinline__ void stage32(const float* __restrict__ src,
                                        char* Xh, char* Xl, uint32_t off) {
    #pragma unroll
    for (int i = 0; i < 8; ++i) {
        float4 t = reinterpret_cast<const float4*>(src)[i];
        uint32_t r0, r1, r2, r3;
        float h0 = bf16hi_rn(t.x, r0), h1 = bf16hi_rn(t.y, r1);
        float h2 = bf16hi_rn(t.z, r2), h3 = bf16hi_rn(t.w, r3);
        uint2 hh = make_uint2(__byte_perm(r0, r1, 0x7632), __byte_perm(r2, r3, 0x7632));
        uint2 ll = make_uint2(bf16x2_of(t.x - h0, t.y - h1), bf16x2_of(t.z - h2, t.w - h3));
        *reinterpret_cast<uint2*>(Xh + off + i * 8) = hh;
        *reinterpret_cast<uint2*>(Xl + off + i * 8) = ll;
    }
}

// ---------------- core MMA helpers ----------------
// one n-group (n=16), 3-term split, single stream (node kernel)
__device__ __forceinline__ void mma6(float* acc, const uint32_t* ah, const uint32_t* al,
                                     const uint32_t* bh, const uint32_t* bl) {
    mma_bf16(acc,     ah, bh[0], bh[1]);
    mma_bf16(acc + 4, ah, bh[2], bh[3]);
    mma_bf16(acc,     ah, bl[0], bl[1]);
    mma_bf16(acc + 4, ah, bl[2], bl[3]);
    mma_bf16(acc,     al, bh[0], bh[1]);
    mma_bf16(acc + 4, al, bh[2], bh[3]);
}
// two streams into the same acc pair, low/high quads interleaved:
// 2 chains x 6 deep, same-acc issue distance 2 (32 cyc). Per-acc op order
// identical to mma6(A);mma6(B) -> bitwise-same results.
__device__ __forceinline__ void mma12(float* acc,
    const uint32_t* ah0, const uint32_t* al0, const uint32_t* bh0, const uint32_t* bl0,
    const uint32_t* ah1, const uint32_t* al1, const uint32_t* bh1, const uint32_t* bl1)
{
    mma_bf16(acc,     ah0, bh0[0], bh0[1]);
    mma_bf16(acc + 4, ah0, bh0[2], bh0[3]);
    mma_bf16(acc,     ah0, bl0[0], bl0[1]);
    mma_bf16(acc + 4, ah0, bl0[2], bl0[3]);
    mma_bf16(acc,     al0, bh0[0], bh0[1]);
    mma_bf16(acc + 4, al0, bh0[2], bh0[3]);
    mma_bf16(acc,     ah1, bh1[0], bh1[1]);
    mma_bf16(acc + 4, ah1, bh1[2], bh1[3]);
    mma_bf16(acc,     ah1, bl1[0], bl1[1]);
    mma_bf16(acc + 4, ah1, bl1[2], bl1[3]);
    mma_bf16(acc,     al1, bh1[0], bh1[1]);
    mma_bf16(acc + 4, al1, bh1[2], bh1[3]);
}
// one stream, two n-groups interleaved: 4 chains x 3 deep, distance 4 (64 cyc)
__device__ __forceinline__ void mma6p(float* a0, float* a1,
    const uint32_t* ah, const uint32_t* al,
    const uint32_t* bh0, const uint32_t* bl0,
    const uint32_t* bh1, const uint32_t* bl1)
{
    mma_bf16(a0,     ah, bh0[0], bh0[1]);
    mma_bf16(a0 + 4, ah, bh0[2], bh0[3]);
    mma_bf16(a1,     ah, bh1[0], bh1[1]);
    mma_bf16(a1 + 4, ah, bh1[2], bh1[3]);
    mma_bf16(a0,     ah, bl0[0], bl0[1]);
    mma_bf16(a0 + 4, ah, bl0[2], bl0[3]);
    mma_bf16(a1,     ah, bl1[0], bl1[1]);
    mma_bf16(a1 + 4, ah, bl1[2], bl1[3]);
    mma_bf16(a0,     al, bh0[0], bh0[1]);
    mma_bf16(a0 + 4, al, bh0[2], bh0[3]);
    mma_bf16(a1,     al, bh1[0], bh1[1]);
    mma_bf16(a1 + 4, al, bh1[2], bh1[3]);
}
// n-group sweep with in-loop LDSM (node kernel)
__device__ __forceinline__ void gemm_groups(float* acc, const uint32_t* ah, const uint32_t* al,
                                            uint32_t baseH, uint32_t baseL, int ngroups)
{
    #pragma unroll
    for (int g = 0; g < 8; ++g) {
        if (g >= ngroups) break;
        uint32_t bh[4], bl[4];
        LDSM4(bh, baseH + g * (16 * ST * 2));
        LDSM4(bl, baseL + g * (16 * ST * 2));
        mma6(acc + 8 * g, ah, al, bh, bl);
    }
}

// ================= prep 1: W1a' = W1a @ P_w (emit bf16 image 0), b1' =================
__global__ void __launch_bounds__(128, 1)
ecat_compose(const float* __restrict__ W1, const float* __restrict__ P_w,
             const float* __restrict__ P_b, const float* __restrict__ b1)
{
    __shared__ float srow[128];
    int o = blockIdx.x;          // 0..127 output row
    int j = threadIdx.x;         // 0..127 output col
    srow[j] = W1[o * 256 + j];   // W1a row o
    __syncthreads();
    float acc = 0.f;
    #pragma unroll 4
    for (int i = 0; i < 128; ++i)
        acc += srow[i] * P_w[i * 128 + j];
    // emit element (o, j) of gWimg[0] hi/lo
    uint32_t hb;
    float h = bf16hi_rn(acc, hb);
    uint32_t lo = bf16x2_of(acc - h, 0.f) & 0xFFFFu;
    reinterpret_cast<uint16_t*>(gWimg[0][0])[o * ST + j] = (uint16_t)(hb >> 16);
    reinterpret_cast<uint16_t*>(gWimg[0][1])[o * ST + j] = (uint16_t)lo;
    if (j == 0) {
        float s = 0.f;
        for (int i = 0; i < 128; ++i) s += srow[i] * P_b[i];
        gB1p[o] = b1[o] + s;
    }
}

// ================= prep 2: W1b, W2, U_w, V_w -> bf16 hi/lo smem images =================
__global__ void __launch_bounds__(PTH, 1)
ecat_convert(const float* __restrict__ W1, const float* __restrict__ W2,
             const float* __restrict__ U_w, const float* __restrict__ V_w)
{
    int b = blockIdx.x;          // 0..3 -> images 1..4
    int tid = threadIdx.x;
    int o = tid >> 2, qo = (tid & 3) * 32;
    const float* srcRow;
    if (b == 0)      srcRow = W1 + o * 256 + 128 + qo;          // W1b
    else if (b == 1) srcRow = W2 + o * 128 + qo;
    else if (b == 2) srcRow = U_w + (size_t)o * 128 + qo;
    else             srcRow = V_w + (size_t)o * 128 + qo;
    stage32(srcRow, (char*)gWimg[b + 1][0], (char*)gWimg[b + 1][1],
            (uint32_t)(o * ST + qo) * 2);
}

// ================= prep 3: VU = V@U_w^T, VV = V@V_w^T (persistent, m=16/warp) =================
__global__ void __launch_bounds__(NTH, 1)
ecat_node(const float* __restrict__ V, int n_nodes, int n_ntiles)
{
    extern __shared__ char sm[];
    uint32_t smb = smem_u32(sm);
    const char* gsrc = &gWimg[3][0][0];
    #pragma unroll
    for (int i = 0; i < 17; ++i) {
        int idx = i * NTH + threadIdx.x;
        CP16(smb + idx * 16, gsrc + idx * 16);   // 17*512 = 8704 chunks exactly
    }
    CP_COMMIT(); CP_WAIT();
    __syncthreads();

    const int tid = threadIdx.x, lane = tid & 31, w = tid >> 5;
    const int r0 = lane >> 2, il = lane & 3, cb = il * 2;
    const uint32_t offB = (uint32_t)(((lane & 7) + (((lane >> 4) & 1) << 3)) * ST
                                     + (((lane >> 3) & 1) << 3)) * 2;

    for (int t = blockIdx.x; t < n_ntiles; t += gridDim.x) {
        int n0 = t * 256 + w * 16 + r0;
        int n1 = n0 + 8;
        int n0c = n0 < n_nodes ? n0 : 0;
        int n1c = n1 < n_nodes ? n1 : 0;
        const float2* pa0 = reinterpret_cast<const float2*>(V + (size_t)n0c * 128);
        const float2* pa1 = reinterpret_cast<const float2*>(V + (size_t)n1c * 128);

        #pragma unroll 1
        for (int pass = 0; pass < 2; ++pass) {
            uint32_t bH = smb + pass * 2 * TILEB, bL = bH + TILEB;
            float acc[64];
            #pragma unroll
            for (int i = 0; i < 64; ++i) acc[i] = 0.f;
            #pragma unroll 1
            for (int ks = 0; ks < 8; ++ks) {
                int i0 = il + 8 * ks, i1 = i0 + 4;
                float2 a0 = pa0[i0], b0 = pa1[i0], c0 = pa0[i1], d0 = pa1[i1];
                uint32_t ah[4], al[4];
                split2(a0.x, a0.y, ah[0], al[0]);
                split2(b0.x, b0.y, ah[1], al[1]);
                split2(c0.x, c0.y, ah[2], al[2]);
                split2(d0.x, d0.y, ah[3], al[3]);
                gemm_groups(acc, ah, al, bH + offB + ks * 32, bL + offB + ks * 32, 8);
            }
            float* dstb = pass ? gVV : gVU;
            #pragma unroll
            for (int nf = 0; nf < 16; ++nf) {
                int c = nf * 8 + cb;
                if (n0 < n_nodes)
                    *reinterpret_cast<float2*>(dstb + (size_t)n0 * 128 + c) =
                        make_float2(acc[nf*4], acc[nf*4+1]);
                if (n1 < n_nodes)
                    *reinterpret_cast<float2*>(dstb + (size_t)n1 * 128 + c) =
                        make_float2(acc[nf*4+2], acc[nf*4+3]);
            }
        }
    }
}

// ================= main edge kernel: persistent, merged A+B, chain-interleaved =================
__global__ void __launch_bounds__(NTH, 1)
ecat_edge(const float* __restrict__ E, const int* __restrict__ src,
          const int* __restrict__ dst, const float* __restrict__ b2,
          float* __restrict__ out, int n_tiles)
{
    extern __shared__ char sm[];
    uint32_t smb = smem_u32(sm);
    const char* gsrc = &gWimg[0][0][0];
    #pragma unroll
    for (int i = 0; i < 26; ++i) {
        int idx = i * NTH + threadIdx.x;
        if (idx < 6 * TILEB / 16) CP16(smb + idx * 16, gsrc + idx * 16);
    }
    CP_COMMIT(); CP_WAIT();
    __syncthreads();

    const int tid = threadIdx.x, lane = tid & 31, w = tid >> 5;
    const int r0 = lane >> 2, il = lane & 3, cb = il * 2;
    const uint32_t offB = (uint32_t)(((lane & 7) + (((lane >> 4) & 1) << 3)) * ST
                                     + (((lane >> 3) & 1) << 3)) * 2;
    const uint32_t uW1aH = smb,             uW1aL = smb + TILEB;
    const uint32_t uW1bH = smb + 2 * TILEB, uW1bL = smb + 3 * TILEB;
    const uint32_t uW2H  = smb + 4 * TILEB, uW2L  = smb + 5 * TILEB;

    for (int t = blockIdx.x; t < n_tiles; t += gridDim.x) {
        long er0 = (long)t * 256 + w * 16 + r0;
        long er1 = er0 + 8;
        int s0 = __ldg(src + er0), s1 = __ldg(src + er1);
        int d0 = __ldg(dst + er0), d1 = __ldg(dst + er1);
        const float2* pu0 = reinterpret_cast<const float2*>(gVU + (size_t)s0 * 128);
        const float2* pu1 = reinterpret_cast<const float2*>(gVU + (size_t)s1 * 128);
        const float2* pv0 = reinterpret_cast<const float2*>(gVV + (size_t)d0 * 128);
        const float2* pv1 = reinterpret_cast<const float2*>(gVV + (size_t)d1 * 128);
        const float2* pe0 = reinterpret_cast<const float2*>(E + er0 * 128);
        const float2* pe1 = reinterpret_cast<const float2*>(E + er1 * 128);

        float acc[64];
        #pragma unroll
        for (int i = 0; i < 64; ++i) acc[i] = 0.f;

        // ---- merged GEMM A+B with interleaved accumulation chains ----
        #pragma unroll 1
        for (int ks = 0; ks < 8; ++ks) {
            int i0 = il + 8 * ks, i1 = i0 + 4;
            uint32_t ath[4], atl[4], aeh[4], ael[4];
            {
                float2 u0 = pu0[i0], u1 = pu1[i0], u2 = pu0[i1], u3 = pu1[i1];
                float2 v0 = pv0[i0], v1 = pv1[i0], v2 = pv0[i1], v3 = pv1[i1];
                split2(fast_tanh(u0.x * v0.x), fast_tanh(u0.y * v0.y), ath[0], atl[0]);
                split2(fast_tanh(u1.x * v1.x), fast_tanh(u1.y * v1.y), ath[1], atl[1]);
                split2(fast_tanh(u2.x * v2.x), fast_tanh(u2.y * v2.y), ath[2], atl[2]);
                split2(fast_tanh(u3.x * v3.x), fast_tanh(u3.y * v3.y), ath[3], atl[3]);
            }
            {
                float2 e0 = pe0[i0], e1 = pe1[i0], e2 = pe0[i1], e3 = pe1[i1];
                split2(lk(e0.x), lk(e0.y), aeh[0], ael[0]);
                split2(lk(e1.x), lk(e1.y), aeh[1], ael[1]);
                split2(lk(e2.x), lk(e2.y), aeh[2], ael[2]);
                split2(lk(e3.x), lk(e3.y), aeh[3], ael[3]);
            }
            const uint32_t bAH = uW1aH + offB + ks * 32, bAL = uW1aL + offB + ks * 32;
            const uint32_t bBH = uW1bH + offB + ks * 32, bBL = uW1bL + offB + ks * 32;
            #pragma unroll
            for (int g = 0; g < 8; ++g) {
                uint32_t go = (uint32_t)g * (16 * ST * 2);
                uint32_t bha[4], bla[4], bhb[4], blb[4];
                LDSM4(bha, bAH + go);
                LDSM4(bhb, bBH + go);
                LDSM4(bla, bAL + go);
                LDSM4(blb, bBL + go);
                mma12(acc + 8 * g, ath, atl, bha, bla, aeh, ael, bhb, blb);
            }
        }

        // ---- y1 = relu(acc + b1'): repack C-frags directly into GEMM-C A-frags ----
        uint32_t yh[8][4], yl[8][4];
        #pragma unroll
        for (int ks = 0; ks < 8; ++ks) {
            #pragma unroll
            for (int p = 0; p < 2; ++p) {
                int nf = 2 * ks + p;
                float2 bb = __ldg(reinterpret_cast<const float2*>(gB1p + nf * 8 + cb));
                split2(fmaxf(acc[nf*4+0] + bb.x, 0.f), fmaxf(acc[nf*4+1] + bb.y, 0.f),
                       yh[ks][2*p], yl[ks][2*p]);
                split2(fmaxf(acc[nf*4+2] + bb.x, 0.f), fmaxf(acc[nf*4+3] + bb.y, 0.f),
                       yh[ks][2*p+1], yl[ks][2*p+1]);
            }
        }

        // ---- GEMM C: out = relu(y1 @ W2^T + b2), n in halves, g-pair interleave ----
        #pragma unroll 1
        for (int h = 0; h < 2; ++h) {
            float acc2[32];
            #pragma unroll
            for (int i = 0; i < 32; ++i) acc2[i] = 0.f;
            uint32_t hb = (uint32_t)h * (64 * ST * 2);
            #pragma unroll 1
            for (int ks = 0; ks < 8; ++ks) {
                const uint32_t bHk = uW2H + offB + hb + ks * 32;
                const uint32_t bLk = uW2L + offB + hb + ks * 32;
                #pragma unroll
                for (int gp = 0; gp < 2; ++gp) {
                    uint32_t go0 = (uint32_t)(2 * gp)     * (16 * ST * 2);
                    uint32_t go1 = (uint32_t)(2 * gp + 1) * (16 * ST * 2);
                    uint32_t bh0[4], bl0[4], bh1[4], bl1[4];
                    LDSM4(bh0, bHk + go0);
                    LDSM4(bh1, bHk + go1);
                    LDSM4(bl0, bLk + go0);
                    LDSM4(bl1, bLk + go1);
                    mma6p(acc2 + 16 * gp, acc2 + 16 * gp + 8,
                          yh[ks], yl[ks], bh0, bl0, bh1, bl1);
                }
            }
            #pragma unroll
            for (int nf = 0; nf < 8; ++nf) {
                int c = h * 64 + nf * 8 + cb;
                float2 bb = __ldg(reinterpret_cast<const float2*>(b2 + c));
                *reinterpret_cast<float2*>(out + er0 * 128 + c) =
                    make_float2(fmaxf(acc2[nf*4+0] + bb.x, 0.f),
                                fmaxf(acc2[nf*4+1] + bb.y, 0.f));
                *reinterpret_cast<float2*>(out + er1 * 128 + c) =
                    make_float2(fmaxf(acc2[nf*4+2] + bb.x, 0.f),
                                fmaxf(acc2[nf*4+3] + bb.y, 0.f));
            }
        }
    }
}

// ================= host =================
extern "C" void kernel_launch(void* const* d_in, const int* in_sizes, int n_in,
                              void* d_out, int out_size)
{
    const float* V   = (const float*)d_in[0];
    const float* E   = (const float*)d_in[1];
    const int*   src = (const int*)d_in[2];
    const int*   dst = (const int*)d_in[3];
    const float* U_w = (const float*)d_in[4];
    const float* V_w = (const float*)d_in[5];
    const float* P_w = (const float*)d_in[6];
    const float* P_b = (const float*)d_in[7];
    const float* W1  = (const float*)d_in[8];
    const float* b1  = (const float*)d_in[9];
    const float* W2  = (const float*)d_in[10];
    const float* b2  = (const float*)d_in[11];
    float* out = (float*)d_out;

    int n_nodes = in_sizes[0] / 128;
    int n_edges = in_sizes[2];
    int n_tiles = n_edges / 256;                 // 2500
    int n_ntiles = (n_nodes + 255) / 256;        // 391

    static int sms = 0;
    if (!sms) {
        cudaDeviceGetAttribute(&sms, cudaDevAttrMultiProcessorCount, 0);
        cudaFuncSetAttribute(ecat_node, cudaFuncAttributeMaxDynamicSharedMemorySize, NODE_SMEM);
        cudaFuncSetAttribute(ecat_edge, cudaFuncAttributeMaxDynamicSharedMemorySize, EDGE_SMEM);
    }

    ecat_compose<<<128, 128>>>(W1, P_w, P_b, b1);
    ecat_convert<<<4, PTH>>>(W1, W2, U_w, V_w);
    ecat_node<<<sms, NTH, NODE_SMEM>>>(V, n_nodes, n_ntiles);
    ecat_edge<<<sms, NTH, EDGE_SMEM>>>(E, src, dst, b2, out, n_tiles);
}